// round 10
// baseline (speedup 1.0000x reference)
#include <cuda_runtime.h>
#include <cuda_fp16.h>
#include <cstdint>
#include <cstddef>

// ---------------------------------------------------------------------------
// Portable PTX helpers (base sm_103 target: no 'a'-suffix instructions)
// ---------------------------------------------------------------------------
__device__ __forceinline__ uint32_t smem_u32(const void* p) {
    uint32_t a;
    asm("{ .reg .u64 t; cvta.to.shared.u64 t, %1; cvt.u32.u64 %0, t; }"
        : "=r"(a) : "l"(p));
    return a;
}
__device__ __forceinline__ float tanh_fast(float x) {
    float y;
    asm("tanh.approx.f32 %0, %1;" : "=f"(y) : "f"(x));
    return y;
}
__device__ __forceinline__ float sig_fast(float x) {
    return fmaf(0.5f, tanh_fast(0.5f * x), 0.5f);
}
// pack two f32 -> f16x2 {lo, hi}
__device__ __forceinline__ uint32_t f16x2(float hi, float lo) {
    uint32_t r;
    asm("cvt.rn.f16x2.f32 %0, %1, %2;" : "=r"(r) : "f"(hi), "f"(lo));
    return r;
}
__device__ __forceinline__ void ldmatrix_x4(uint32_t& r0, uint32_t& r1,
                                            uint32_t& r2, uint32_t& r3,
                                            uint32_t addr) {
    asm volatile("ldmatrix.sync.aligned.m8n8.x4.shared.b16 {%0,%1,%2,%3}, [%4];"
                 : "=r"(r0), "=r"(r1), "=r"(r2), "=r"(r3) : "r"(addr));
}
__device__ __forceinline__ void mma16816(float* d, uint32_t a0, uint32_t a1,
                                         uint32_t a2, uint32_t a3,
                                         uint32_t b0, uint32_t b1) {
    asm volatile(
        "mma.sync.aligned.m16n8k16.row.col.f32.f16.f16.f32 "
        "{%0,%1,%2,%3}, {%4,%5,%6,%7}, {%8,%9}, {%0,%1,%2,%3};"
        : "+f"(d[0]), "+f"(d[1]), "+f"(d[2]), "+f"(d[3])
        : "r"(a0), "r"(a1), "r"(a2), "r"(a3), "r"(b0), "r"(b1));
}
__device__ __forceinline__ uint32_t sw128(uint32_t off) {
    return off ^ ((off >> 3) & 0x70);
}

// ---------------------------------------------------------------------------
// Problem constants
// ---------------------------------------------------------------------------
#define B_    4
#define T_    32
#define H_    64
#define W_    64
#define COUT_ 64
#define HW_   4096

// K layout: pair p = j = ci*9+kh*3+kw (0..26), halves = kd {t-1, t}.
// Pair 27: A = {1.0, 0}, B = {bias, 0}. Pairs 28..31 zero.
// B row n: tile8=n>>3, jj=n&7 -> cout c=(tile8>>1)*4+(jj>>1), gate=(tile8&1)*2+(jj&1)

// SMEM layout (bytes)
#define SM_B_OFF    0                    // B fp16 [256 n][128 B]     = 32768
#define SM_A0_OFF   32768                // A fp16 buffer 0           = 16384
#define SM_A1_OFF   49152                // A fp16 buffer 1           = 16384
#define SM_HALO_OFF 65536                // halo 540 float2 (parity)  = 4320
#define SM_TOTAL    69856

#define CT_ 512

__global__ void __launch_bounds__(CT_, 1)
fused_mma_kernel(const float* __restrict__ X,
                 const float* __restrict__ Wc, const float* __restrict__ bconv,
                 const float* __restrict__ Wci, const float* __restrict__ Wcf,
                 const float* __restrict__ Wco, float* __restrict__ out) {
    extern __shared__ __align__(1024) char sm[];
    const uint32_t smb = smem_u32(sm);
    float2* hsm2 = (float2*)(sm + SM_HALO_OFF);  // [idx].x = even plane, .y = odd

    const int tid  = threadIdx.x;
    const int wid  = tid >> 5;
    const int lane = tid & 31;
    const int wm   = wid & 3;                   // M-quarter: 32 px
    const int nq   = wid >> 2;                  // N-quarter: 64 gate rows
    const int tile = blockIdx.x;
    const int b    = blockIdx.y;
    const int trow = (tile >> 3) * 16;
    const int tcol = (tile & 7) * 8;

    const float* Xb = X + (size_t)b * 3 * T_ * HW_;

    // ---- prologue: B weights + bias (fp16, SW128), A const cols in BOTH bufs ----
    for (int i = tid; i < 256 * 32; i += CT_) {
        int n = i >> 5;
        int p = i & 31;
        int tile8 = n >> 3;
        int jj    = n & 7;
        int c     = (tile8 >> 1) * 4 + (jj >> 1);
        int gate  = (tile8 & 1) * 2 + (jj & 1);
        int o     = gate * 64 + c;
        float v0 = 0.f, v1 = 0.f;
        if (p < 27) {
            int ci  = p / 9;
            int khw = p - ci * 9;
            v0 = Wc[o * 54 + ci * 18 + khw];
            v1 = Wc[o * 54 + ci * 18 + 9 + khw];
        } else if (p == 27) {
            v0 = bconv[o];
        }
        *(uint32_t*)(sm + SM_B_OFF + sw128((uint32_t)(n * 128 + p * 4))) = f16x2(v1, v0);
    }
    for (int i = tid; i < 128 * 5; i += CT_) {
        int px = i / 5;
        int p  = 27 + (i - px * 5);
        uint32_t v = (p == 27) ? f16x2(0.f, 1.f) : 0u;
        uint32_t arel = sw128((uint32_t)(px * 128 + p * 4));
        *(uint32_t*)(sm + SM_A0_OFF + arel) = v;
        *(uint32_t*)(sm + SM_A1_OFF + arel) = v;
    }

    // ---- halo prefetch descriptors (t-invariant) ----
    int h0idx, h0goff; bool h0ok;
    {
        int i  = tid;                   // 0..511 < 540
        int ci = i / 180;
        int rem = i - ci * 180;
        int rr = rem / 10;
        int cc = rem - rr * 10;
        int hh = trow - 1 + rr;
        int ww = tcol - 1 + cc;
        h0ok   = (hh >= 0 && hh < H_ && ww >= 0 && ww < W_);
        h0idx  = i;
        h0goff = ci * (T_ * HW_) + hh * W_ + ww;
    }
    int h1idx = 0, h1goff = 0; bool h1ok = false;
    if (tid < 28) {
        int i  = tid + 512;
        int ci = i / 180;
        int rem = i - ci * 180;
        int rr = rem / 10;
        int cc = rem - rr * 10;
        int hh = trow - 1 + rr;
        int ww = tcol - 1 + cc;
        h1ok   = (hh >= 0 && hh < H_ && ww >= 0 && ww < W_);
        h1idx  = i;
        h1goff = ci * (T_ * HW_) + hh * W_ + ww;
    }
    // plane 0 -> comp .x (parity 0); x(-1) = 0 -> comp .y
    hsm2[h0idx] = make_float2(h0ok ? Xb[h0goff] : 0.f, 0.f);
    if (tid < 28) hsm2[h1idx] = make_float2(h1ok ? Xb[h1goff] : 0.f, 0.f);

    // ---- A-build descriptors packed: (swizzled A-rel offset << 10) | halo idx ----
    uint32_t adesc[7];
#pragma unroll
    for (int k = 0; k < 7; k++) {
        int i = tid + k * CT_;
        if (i < 128 * 27) {
            int px = i / 27;
            int p  = i - px * 27;
            int ci  = p / 9;
            int khw = p - ci * 9;
            int kh  = khw / 3;
            int kw  = khw - kh * 3;
            uint32_t asoff = (uint32_t)(ci * 180 + ((px >> 3) + kh) * 10 + ((px & 7) + kw));
            uint32_t arel  = sw128((uint32_t)(px * 128 + p * 4));
            adesc[k] = (arel << 10) | asoff;
        } else {
            adesc[k] = 0xFFFFFFFFu;
        }
    }

    // ---- peephole params -> fp16 registers ----
    const int q  = lane & 3;
    const int lr = lane >> 2;
    const int r8 = lane & 7;
    const int g  = lane >> 3;
    const int hw0 = (trow + wm * 4) * 64 + tcol + lr;

    __half2 wifh[16];
    __half2 wcoh[8];
    {
        float wcot[16];
#pragma unroll
        for (int m = 0; m < 16; m++) {
            int quarter = m >> 2;
            int krow    = m & 3;
            int c   = (nq * 4 + quarter) * 4 + q;
            int hwm = hw0 + krow * 64;
            wifh[m] = __floats2half2_rn(Wci[c * HW_ + hwm], Wcf[c * HW_ + hwm]);
            wcot[m] = Wco[c * HW_ + hwm];
        }
#pragma unroll
        for (int j = 0; j < 8; j++)
            wcoh[j] = __floats2half2_rn(wcot[2 * j], wcot[2 * j + 1]);
    }
    __syncthreads();

    // ---- prologue A-build(0) into buf 0: v1 = x(0) (.x), v0 = x(-1) (.y) ----
#pragma unroll
    for (int k = 0; k < 7; k++) {
        uint32_t d = adesc[k];
        if (d != 0xFFFFFFFFu) {
            float2 f = hsm2[d & 1023];
            *(uint32_t*)(sm + SM_A0_OFF + (d >> 10)) = f16x2(f.x, f.y);
        }
    }
    // prefetch halo plane 1
    float pf0 = 0.f, pf1 = 0.f;
    if (h0ok) pf0 = Xb[h0goff + HW_];
    if (tid < 28 && h1ok) pf1 = Xb[h1goff + HW_];

    // ---- lane-constant ldmatrix addresses ----
    const uint32_t cL  = (uint32_t)r8 << 4;
    const uint32_t dkA = (uint32_t)(g >> 1) * 16;
    const uint32_t dkB = (uint32_t)(g & 1) * 16;
    const uint32_t aR0 = (uint32_t)(wm * 32 + r8 + 8 * (g & 1)) * 128;   // buf-relative
    const uint32_t bB  = smb + SM_B_OFF + (uint32_t)(nq * 64 + r8 + 8 * (g >> 1)) * 128;

    // ---- output base pointers (one per quarter) ----
    float* outq[4];
#pragma unroll
    for (int quarter = 0; quarter < 4; quarter++) {
        int c = (nq * 4 + quarter) * 4 + q;
        outq[quarter] = out + ((size_t)(b * COUT_ + c)) * (T_ * HW_) + hw0;
    }

    float C[16];
#pragma unroll
    for (int m = 0; m < 16; m++) C[m] = 0.f;

    const uint32_t haloB = smb + SM_HALO_OFF;

    for (int t = 0; t < T_; t++) {
        const uint32_t pt = (uint32_t)((t + 1) & 1);

        // ---- store halo(t+1) (prefetched last iter) into parity comp pt ----
        if (t + 1 < T_) {
            *(float*)(sm + SM_HALO_OFF + h0idx * 8 + pt * 4) = pf0;
            if (tid < 28) *(float*)(sm + SM_HALO_OFF + h1idx * 8 + pt * 4) = pf1;
        }
        __syncthreads();   // A(t) built + halo(t+1) visible

        // ---- load ALL A fragments for t from buf[t&1] ----
        const uint32_t aB0 = smb + (uint32_t)SM_A0_OFF + (uint32_t)(t & 1) * 16384 + aR0;
        const uint32_t aB1 = aB0 + 16 * 128;
        uint32_t af[32];
#pragma unroll
        for (int kc = 0; kc < 4; kc++) {
            uint32_t ko = (((uint32_t)kc * 32) + dkA) ^ cL;
            ldmatrix_x4(af[kc * 8], af[kc * 8 + 1], af[kc * 8 + 2], af[kc * 8 + 3],
                        aB0 + ko);
            ldmatrix_x4(af[kc * 8 + 4], af[kc * 8 + 5], af[kc * 8 + 6], af[kc * 8 + 7],
                        aB1 + ko);
        }

        // ---- prefetch halo plane t+2 (consumed next iteration) ----
        if (t + 2 < T_) {
            const int toff = (t + 2) * HW_;
            pf0 = h0ok ? Xb[h0goff + toff] : 0.f;
            if (tid < 28) pf1 = h1ok ? Xb[h1goff + toff] : 0.f;
        }

        // ---- A-build(t+1) into buf[pt] — overlaps MMA + recurrence below ----
        if (t + 1 < T_) {
            const uint32_t abase = (uint32_t)SM_A0_OFF + pt * 16384;
#pragma unroll
            for (int k = 0; k < 7; k++) {
                uint32_t d = adesc[k];
                if (d != 0xFFFFFFFFu) {
                    float2 f = hsm2[d & 1023];
                    float v1 = pt ? f.y : f.x;    // x(t+1)
                    float v0 = pt ? f.x : f.y;    // x(t)
                    *(uint32_t*)(sm + abase + (d >> 10)) = f16x2(v1, v0);
                }
            }
        }

        // ---- MMA + recurrence per N-quarter ----
        const size_t tof = (size_t)t * HW_;
#pragma unroll
        for (int quarter = 0; quarter < 4; quarter++) {
            float acc[16];
#pragma unroll
            for (int m = 0; m < 16; m++) acc[m] = 0.f;

            const uint32_t bq = bB + (uint32_t)quarter * 2048;
#pragma unroll
            for (int kc = 0; kc < 4; kc++) {
                uint32_t b0, b1, b2, b3;
                ldmatrix_x4(b0, b1, b2, b3, bq + ((((uint32_t)kc * 32) + dkB) ^ cL));
                mma16816(acc,      af[kc*8],   af[kc*8+1], af[kc*8+2], af[kc*8+3], b0, b1);
                mma16816(acc + 4,  af[kc*8],   af[kc*8+1], af[kc*8+2], af[kc*8+3], b2, b3);
                mma16816(acc + 8,  af[kc*8+4], af[kc*8+5], af[kc*8+6], af[kc*8+7], b0, b1);
                mma16816(acc + 12, af[kc*8+4], af[kc*8+5], af[kc*8+6], af[kc*8+7], b2, b3);
            }

            float* op = outq[quarter] + tof;
#pragma unroll
            for (int krow = 0; krow < 4; krow++) {
                const int m    = quarter * 4 + krow;
                const int base = (krow >> 1) * 8 + (krow & 1) * 2;
                float iv = acc[base];
                float fv = acc[base + 1];
                float gv = acc[base + 4];
                float ov = acc[base + 5];
                float2 wif = __half22float2(wifh[m]);
                float wco  = (krow & 1) ? __high2float(wcoh[m >> 1])
                                        : __low2float(wcoh[m >> 1]);
                float Cp = C[m];
                float ig = sig_fast(iv + wif.x * Cp);
                float fg = sig_fast(fv + wif.y * Cp);
                float Cn = fg * Cp + ig * tanh_fast(gv);
                float og = sig_fast(ov + wco * Cn);
                op[krow * 64] = og * tanh_fast(Cn);
                C[m] = Cn;
            }
        }
        __syncthreads();   // A-build(t+1) + af-loads done before next overwrite
    }
    (void)haloB;
}

// ---------------------------------------------------------------------------
// kernel_launch
// ---------------------------------------------------------------------------
extern "C" void kernel_launch(void* const* d_in, const int* in_sizes, int n_in,
                              void* d_out, int out_size) {
    const float* X     = (const float*)d_in[0];
    const float* Wc    = (const float*)d_in[1];
    const float* bconv = (const float*)d_in[2];
    const float* Wci   = (const float*)d_in[3];
    const float* Wcf   = (const float*)d_in[4];
    const float* Wco   = (const float*)d_in[5];
    float* out = (float*)d_out;

    cudaFuncSetAttribute(fused_mma_kernel, cudaFuncAttributeMaxDynamicSharedMemorySize,
                         SM_TOTAL);

    dim3 grid(32, B_);   // 32 tiles x 4 batches = 128 CTAs (one wave)
    fused_mma_kernel<<<grid, CT_, SM_TOTAL>>>(X, Wc, bconv, Wci, Wcf, Wco, out);
}

// round 11
// speedup vs baseline: 1.1373x; 1.1373x over previous
#include <cuda_runtime.h>
#include <cuda_fp16.h>
#include <cstdint>
#include <cstddef>

// ---------------------------------------------------------------------------
// Portable PTX helpers (base sm_103 target: no 'a'-suffix instructions)
// ---------------------------------------------------------------------------
__device__ __forceinline__ uint32_t smem_u32(const void* p) {
    uint32_t a;
    asm("{ .reg .u64 t; cvta.to.shared.u64 t, %1; cvt.u32.u64 %0, t; }"
        : "=r"(a) : "l"(p));
    return a;
}
__device__ __forceinline__ float tanh_fast(float x) {
    float y;
    asm("tanh.approx.f32 %0, %1;" : "=f"(y) : "f"(x));
    return y;
}
__device__ __forceinline__ float sig_fast(float x) {
    return fmaf(0.5f, tanh_fast(0.5f * x), 0.5f);
}
// pack two f32 -> f16x2 {lo, hi}  (same operand convention as validated rounds)
__device__ __forceinline__ uint32_t f16x2(float hi, float lo) {
    uint32_t r;
    asm("cvt.rn.f16x2.f32 %0, %1, %2;" : "=r"(r) : "f"(hi), "f"(lo));
    return r;
}
__device__ __forceinline__ void ldmatrix_x4(uint32_t& r0, uint32_t& r1,
                                            uint32_t& r2, uint32_t& r3,
                                            uint32_t addr) {
    asm volatile("ldmatrix.sync.aligned.m8n8.x4.shared.b16 {%0,%1,%2,%3}, [%4];"
                 : "=r"(r0), "=r"(r1), "=r"(r2), "=r"(r3) : "r"(addr));
}
__device__ __forceinline__ void ldmatrix_x2(uint32_t& r0, uint32_t& r1,
                                            uint32_t addr) {
    asm volatile("ldmatrix.sync.aligned.m8n8.x2.shared.b16 {%0,%1}, [%2];"
                 : "=r"(r0), "=r"(r1) : "r"(addr));
}
__device__ __forceinline__ void mma16816(float* d, uint32_t a0, uint32_t a1,
                                         uint32_t a2, uint32_t a3,
                                         uint32_t b0, uint32_t b1) {
    asm volatile(
        "mma.sync.aligned.m16n8k16.row.col.f32.f16.f16.f32 "
        "{%0,%1,%2,%3}, {%4,%5,%6,%7}, {%8,%9}, {%0,%1,%2,%3};"
        : "+f"(d[0]), "+f"(d[1]), "+f"(d[2]), "+f"(d[3])
        : "r"(a0), "r"(a1), "r"(a2), "r"(a3), "r"(b0), "r"(b1));
}
__device__ __forceinline__ void mma16808(float* d, uint32_t a0, uint32_t a1,
                                         uint32_t b0) {
    asm volatile(
        "mma.sync.aligned.m16n8k8.row.col.f32.f16.f16.f32 "
        "{%0,%1,%2,%3}, {%4,%5}, {%6}, {%0,%1,%2,%3};"
        : "+f"(d[0]), "+f"(d[1]), "+f"(d[2]), "+f"(d[3])
        : "r"(a0), "r"(a1), "r"(b0));
}
__device__ __forceinline__ uint32_t sw128(uint32_t off) {
    return off ^ ((off >> 3) & 0x70);
}

// ---------------------------------------------------------------------------
// Problem constants
// ---------------------------------------------------------------------------
#define B_    4
#define T_    32
#define H_    64
#define W_    64
#define COUT_ 64
#define HW_   4096

// K layout: pair p = j = ci*9+kh*3+kw (0..26), halves = kd {t-1, t}.
// Pair 27: A = {1.0, 0}, B = {bias, 0}. Pairs 28..31 zero (never touched by MMA:
// 3 x k16 chunks cover pairs 0..23; one k8 chunk covers pairs 24..27).
// B row n: tile8=n>>3, jj=n&7 -> cout c=(tile8>>1)*4+(jj>>1), gate=(tile8&1)*2+(jj&1)

// SMEM layout (bytes)
#define SM_B_OFF    0                    // B fp16 [256 n][128 B]        = 32768
#define SM_A0_OFF   32768                // A fp16 buffer 0              = 16384
#define SM_A1_OFF   49152                // A fp16 buffer 1              = 16384
#define SM_HALO_OFF 65536                // halo 3 planes x 544 f32      = 6528
#define SM_TOTAL    72064
#define HPLANE      544

#define CT_ 512

__global__ void __launch_bounds__(CT_, 1)
fused_mma_kernel(const float* __restrict__ X,
                 const float* __restrict__ Wc, const float* __restrict__ bconv,
                 const float* __restrict__ Wci, const float* __restrict__ Wcf,
                 const float* __restrict__ Wco, float* __restrict__ out) {
    extern __shared__ __align__(1024) char sm[];
    const uint32_t smb = smem_u32(sm);
    float* hsm = (float*)(sm + SM_HALO_OFF);    // [plane = t mod 3][idx]

    const int tid  = threadIdx.x;
    const int wid  = tid >> 5;
    const int lane = tid & 31;
    const int wm   = wid & 3;                   // M-quarter: 32 px
    const int nq   = wid >> 2;                  // N-quarter: 64 gate rows
    const int tile = blockIdx.x;
    const int b    = blockIdx.y;
    const int trow = (tile >> 3) * 16;
    const int tcol = (tile & 7) * 8;

    const float* Xb = X + (size_t)b * 3 * T_ * HW_;

    // ---- prologue: B weights + bias (fp16, SW128), A const cols in BOTH bufs ----
    for (int i = tid; i < 256 * 32; i += CT_) {
        int n = i >> 5;
        int p = i & 31;
        int tile8 = n >> 3;
        int jj    = n & 7;
        int c     = (tile8 >> 1) * 4 + (jj >> 1);
        int gate  = (tile8 & 1) * 2 + (jj & 1);
        int o     = gate * 64 + c;
        float v0 = 0.f, v1 = 0.f;
        if (p < 27) {
            int ci  = p / 9;
            int khw = p - ci * 9;
            v0 = Wc[o * 54 + ci * 18 + khw];
            v1 = Wc[o * 54 + ci * 18 + 9 + khw];
        } else if (p == 27) {
            v0 = bconv[o];
        }
        *(uint32_t*)(sm + SM_B_OFF + sw128((uint32_t)(n * 128 + p * 4))) = f16x2(v1, v0);
    }
    for (int i = tid; i < 128 * 5; i += CT_) {
        int px = i / 5;
        int p  = 27 + (i - px * 5);
        uint32_t v = (p == 27) ? f16x2(0.f, 1.f) : 0u;
        uint32_t arel = sw128((uint32_t)(px * 128 + p * 4));
        *(uint32_t*)(sm + SM_A0_OFF + arel) = v;
        *(uint32_t*)(sm + SM_A1_OFF + arel) = v;
    }

    // ---- halo prefetch descriptors (t-invariant) ----
    int h0idx, h0goff; bool h0ok;
    {
        int i  = tid;                   // 0..511 < 540
        int ci = i / 180;
        int rem = i - ci * 180;
        int rr = rem / 10;
        int cc = rem - rr * 10;
        int hh = trow - 1 + rr;
        int ww = tcol - 1 + cc;
        h0ok   = (hh >= 0 && hh < H_ && ww >= 0 && ww < W_);
        h0idx  = i;
        h0goff = ci * (T_ * HW_) + hh * W_ + ww;
    }
    int h1idx = 0, h1goff = 0; bool h1ok = false;
    if (tid < 28) {
        int i  = tid + 512;
        int ci = i / 180;
        int rem = i - ci * 180;
        int rr = rem / 10;
        int cc = rem - rr * 10;
        int hh = trow - 1 + rr;
        int ww = tcol - 1 + cc;
        h1ok   = (hh >= 0 && hh < H_ && ww >= 0 && ww < W_);
        h1idx  = i;
        h1goff = ci * (T_ * HW_) + hh * W_ + ww;
    }
    // planes: 0 <- x(0), 1 <- x(1), 2 <- 0 (x(-1); note (-1) mod 3 == 2)
    hsm[h0idx]              = h0ok ? Xb[h0goff] : 0.f;
    hsm[HPLANE + h0idx]     = h0ok ? Xb[h0goff + HW_] : 0.f;
    hsm[2 * HPLANE + h0idx] = 0.f;
    if (tid < 28) {
        hsm[h1idx]              = h1ok ? Xb[h1goff] : 0.f;
        hsm[HPLANE + h1idx]     = h1ok ? Xb[h1goff + HW_] : 0.f;
        hsm[2 * HPLANE + h1idx] = 0.f;
    }

    // ---- A-build descriptors packed: (swizzled A-rel offset << 10) | halo idx ----
    uint32_t adesc[7];
#pragma unroll
    for (int k = 0; k < 7; k++) {
        int i = tid + k * CT_;
        if (i < 128 * 27) {
            int px = i / 27;
            int p  = i - px * 27;
            int ci  = p / 9;
            int khw = p - ci * 9;
            int kh  = khw / 3;
            int kw  = khw - kh * 3;
            uint32_t asoff = (uint32_t)(ci * 180 + ((px >> 3) + kh) * 10 + ((px & 7) + kw));
            uint32_t arel  = sw128((uint32_t)(px * 128 + p * 4));
            adesc[k] = (arel << 10) | asoff;
        } else {
            adesc[k] = 0xFFFFFFFFu;
        }
    }

    // ---- peephole params -> fp16 registers ----
    const int q  = lane & 3;
    const int lr = lane >> 2;
    const int r8 = lane & 7;
    const int g  = lane >> 3;
    const int hw0 = (trow + wm * 4) * 64 + tcol + lr;

    __half2 wifh[16];
    __half2 wcoh[8];
    {
        float wcot[16];
#pragma unroll
        for (int m = 0; m < 16; m++) {
            int quarter = m >> 2;
            int krow    = m & 3;
            int c   = (nq * 4 + quarter) * 4 + q;
            int hwm = hw0 + krow * 64;
            wifh[m] = __floats2half2_rn(Wci[c * HW_ + hwm], Wcf[c * HW_ + hwm]);
            wcot[m] = Wco[c * HW_ + hwm];
        }
#pragma unroll
        for (int j = 0; j < 8; j++)
            wcoh[j] = __floats2half2_rn(wcot[2 * j], wcot[2 * j + 1]);
    }
    __syncthreads();    // halo planes + B staged

    // ---- prologue A-build(0) into buf 0: v0 = x(-1) (plane 2), v1 = x(0) (plane 0) ----
#pragma unroll
    for (int k = 0; k < 7; k++) {
        uint32_t d = adesc[k];
        if (d != 0xFFFFFFFFu) {
            uint32_t off = d & 1023;
            float v0 = hsm[2 * HPLANE + off];
            float v1 = hsm[off];
            *(uint32_t*)(sm + SM_A0_OFF + (d >> 10)) = f16x2(v1, v0);
        }
    }

    // ---- lane-constant ldmatrix addresses ----
    const uint32_t cL  = (uint32_t)r8 << 4;
    const uint32_t dkA = (uint32_t)(g >> 1) * 16;
    const uint32_t dkB = (uint32_t)(g & 1) * 16;
    const uint32_t aR0 = (uint32_t)(wm * 32 + r8 + 8 * (g & 1)) * 128;   // buf-relative
    const uint32_t bB  = smb + SM_B_OFF + (uint32_t)(nq * 64 + r8 + 8 * (g >> 1)) * 128;
    // k8 tail (pairs 24..27 at byte cols 96..111), lanes 0..15 supply rows
    const uint32_t tailOff = 96u ^ cL;
    const uint32_t aRT = (uint32_t)(wm * 32 + (lane & 15)) * 128 + tailOff;  // buf-relative
    const uint32_t bBT = smb + SM_B_OFF + (uint32_t)(nq * 64 + (lane & 15)) * 128 + tailOff;

    // ---- output base ----
    float* outb = out + ((size_t)(b * COUT_ + nq * 16 + q)) * (T_ * HW_) + hw0;
    const size_t qstride = (size_t)4 * (T_ * HW_);   // per quarter (cout += 4)

    float C[16];
#pragma unroll
    for (int m = 0; m < 16; m++) C[m] = 0.f;

    float pf0 = 0.f, pf1 = 0.f;

    for (int t = 0; t < T_; t++) {
        __syncthreads();   // A(t) built; halo plane (t+1)%3 stored; prior reads done

        const int pl0 = t % 3;              // x(t)
        const int pl1 = (t + 1) % 3;        // x(t+1)
        const int pl2 = (t + 2) % 3;        // store target for prefetch

        // ---- load ALL A fragments for t from buf[t&1] ----
        const uint32_t abuf = smb + (uint32_t)SM_A0_OFF + (uint32_t)(t & 1) * 16384;
        const uint32_t aB0 = abuf + aR0;
        const uint32_t aB1 = aB0 + 16 * 128;
        uint32_t af[24];
#pragma unroll
        for (int kc = 0; kc < 3; kc++) {
            uint32_t ko = (((uint32_t)kc * 32) + dkA) ^ cL;
            ldmatrix_x4(af[kc * 8], af[kc * 8 + 1], af[kc * 8 + 2], af[kc * 8 + 3],
                        aB0 + ko);
            ldmatrix_x4(af[kc * 8 + 4], af[kc * 8 + 5], af[kc * 8 + 6], af[kc * 8 + 7],
                        aB1 + ko);
        }
        uint32_t at00, at01, at10, at11;
        ldmatrix_x2(at00, at01, abuf + aRT);
        ldmatrix_x2(at10, at11, abuf + aRT + 16 * 128);

        // ---- prefetch halo plane t+2 (LDG; stored at end of iter) ----
        if (t + 2 < T_) {
            const int toff = (t + 2) * HW_;
            pf0 = h0ok ? Xb[h0goff + toff] : 0.f;
            if (tid < 28) pf1 = h1ok ? Xb[h1goff + toff] : 0.f;
        }

        // ---- A-build(t+1) into buf[(t+1)&1] — overlaps MMA below ----
        if (t + 1 < T_) {
            char* ab = sm + SM_A0_OFF + (size_t)((t + 1) & 1) * 16384;
            const float* hb0 = hsm + pl0 * HPLANE;
            const float* hb1 = hsm + pl1 * HPLANE;
#pragma unroll
            for (int k = 0; k < 7; k++) {
                uint32_t d = adesc[k];
                if (d != 0xFFFFFFFFu) {
                    uint32_t off = d & 1023;
                    float v0 = hb0[off];    // x(t)   (kd=0 for step t+1)
                    float v1 = hb1[off];    // x(t+1) (kd=1)
                    *(uint32_t*)(ab + (d >> 10)) = f16x2(v1, v0);
                }
            }
        }

        // ---- MMA + recurrence per N-quarter ----
        const size_t tof = (size_t)t * HW_;
#pragma unroll
        for (int quarter = 0; quarter < 4; quarter++) {
            float acc[16];
#pragma unroll
            for (int m = 0; m < 16; m++) acc[m] = 0.f;

            const uint32_t bq = bB + (uint32_t)quarter * 2048;
#pragma unroll
            for (int kc = 0; kc < 3; kc++) {
                uint32_t b0, b1, b2, b3;
                ldmatrix_x4(b0, b1, b2, b3, bq + ((((uint32_t)kc * 32) + dkB) ^ cL));
                mma16816(acc,      af[kc*8],   af[kc*8+1], af[kc*8+2], af[kc*8+3], b0, b1);
                mma16816(acc + 4,  af[kc*8],   af[kc*8+1], af[kc*8+2], af[kc*8+3], b2, b3);
                mma16816(acc + 8,  af[kc*8+4], af[kc*8+5], af[kc*8+6], af[kc*8+7], b0, b1);
                mma16816(acc + 12, af[kc*8+4], af[kc*8+5], af[kc*8+6], af[kc*8+7], b2, b3);
            }
            {   // k8 tail: pairs 24..27 (incl. bias)
                uint32_t bt0, bt1;
                ldmatrix_x2(bt0, bt1, bBT + (uint32_t)quarter * 2048);
                mma16808(acc,      at00, at01, bt0);
                mma16808(acc + 4,  at00, at01, bt1);
                mma16808(acc + 8,  at10, at11, bt0);
                mma16808(acc + 12, at10, at11, bt1);
            }

            float* op = outb + (size_t)quarter * qstride + tof;
#pragma unroll
            for (int krow = 0; krow < 4; krow++) {
                const int m    = quarter * 4 + krow;
                const int base = (krow >> 1) * 8 + (krow & 1) * 2;
                float iv = acc[base];
                float fv = acc[base + 1];
                float gv = acc[base + 4];
                float ov = acc[base + 5];
                float2 wif = __half22float2(wifh[m]);
                float wco  = (krow & 1) ? __high2float(wcoh[m >> 1])
                                        : __low2float(wcoh[m >> 1]);
                float Cp = C[m];
                float ig = sig_fast(iv + wif.x * Cp);
                float fg = sig_fast(fv + wif.y * Cp);
                float Cn = fg * Cp + ig * tanh_fast(gv);
                float og = sig_fast(ov + wco * Cn);
                op[krow * 64] = og * tanh_fast(Cn);
                C[m] = Cn;
            }
        }

        // ---- store prefetched halo(t+2) into plane pl2 (retired plane) ----
        if (t + 2 < T_) {
            hsm[pl2 * HPLANE + h0idx] = pf0;
            if (tid < 28) hsm[pl2 * HPLANE + h1idx] = pf1;
        }
    }
}

// ---------------------------------------------------------------------------
// kernel_launch
// ---------------------------------------------------------------------------
extern "C" void kernel_launch(void* const* d_in, const int* in_sizes, int n_in,
                              void* d_out, int out_size) {
    const float* X     = (const float*)d_in[0];
    const float* Wc    = (const float*)d_in[1];
    const float* bconv = (const float*)d_in[2];
    const float* Wci   = (const float*)d_in[3];
    const float* Wcf   = (const float*)d_in[4];
    const float* Wco   = (const float*)d_in[5];
    float* out = (float*)d_out;

    cudaFuncSetAttribute(fused_mma_kernel, cudaFuncAttributeMaxDynamicSharedMemorySize,
                         SM_TOTAL);

    dim3 grid(32, B_);   // 32 tiles x 4 batches = 128 CTAs (one wave)
    fused_mma_kernel<<<grid, CT_, SM_TOTAL>>>(X, Wc, bconv, Wci, Wcf, Wco, out);
}

// round 12
// speedup vs baseline: 1.2373x; 1.0880x over previous
#include <cuda_runtime.h>
#include <cuda_fp16.h>
#include <cstdint>
#include <cstddef>

// ---------------------------------------------------------------------------
// Portable PTX helpers (base sm_103 target: no 'a'-suffix instructions)
// ---------------------------------------------------------------------------
__device__ __forceinline__ uint32_t smem_u32(const void* p) {
    uint32_t a;
    asm("{ .reg .u64 t; cvta.to.shared.u64 t, %1; cvt.u32.u64 %0, t; }"
        : "=r"(a) : "l"(p));
    return a;
}
__device__ __forceinline__ float tanh_fast(float x) {
    float y;
    asm("tanh.approx.f32 %0, %1;" : "=f"(y) : "f"(x));
    return y;
}
__device__ __forceinline__ float sig_fast(float x) {
    return fmaf(0.5f, tanh_fast(0.5f * x), 0.5f);
}
// pack two f32 -> f16x2 {lo, hi}
__device__ __forceinline__ uint32_t f16x2(float hi, float lo) {
    uint32_t r;
    asm("cvt.rn.f16x2.f32 %0, %1, %2;" : "=r"(r) : "f"(hi), "f"(lo));
    return r;
}
__device__ __forceinline__ void ldmatrix_x4(uint32_t& r0, uint32_t& r1,
                                            uint32_t& r2, uint32_t& r3,
                                            uint32_t addr) {
    asm volatile("ldmatrix.sync.aligned.m8n8.x4.shared.b16 {%0,%1,%2,%3}, [%4];"
                 : "=r"(r0), "=r"(r1), "=r"(r2), "=r"(r3) : "r"(addr));
}
__device__ __forceinline__ void ldmatrix_x2(uint32_t& r0, uint32_t& r1,
                                            uint32_t addr) {
    asm volatile("ldmatrix.sync.aligned.m8n8.x2.shared.b16 {%0,%1}, [%2];"
                 : "=r"(r0), "=r"(r1) : "r"(addr));
}
__device__ __forceinline__ void mma16816(float* d, uint32_t a0, uint32_t a1,
                                         uint32_t a2, uint32_t a3,
                                         uint32_t b0, uint32_t b1) {
    asm volatile(
        "mma.sync.aligned.m16n8k16.row.col.f32.f16.f16.f32 "
        "{%0,%1,%2,%3}, {%4,%5,%6,%7}, {%8,%9}, {%0,%1,%2,%3};"
        : "+f"(d[0]), "+f"(d[1]), "+f"(d[2]), "+f"(d[3])
        : "r"(a0), "r"(a1), "r"(a2), "r"(a3), "r"(b0), "r"(b1));
}
__device__ __forceinline__ void mma16808(float* d, uint32_t a0, uint32_t a1,
                                         uint32_t b0) {
    asm volatile(
        "mma.sync.aligned.m16n8k8.row.col.f32.f16.f16.f32 "
        "{%0,%1,%2,%3}, {%4,%5}, {%6}, {%0,%1,%2,%3};"
        : "+f"(d[0]), "+f"(d[1]), "+f"(d[2]), "+f"(d[3])
        : "r"(a0), "r"(a1), "r"(b0));
}
__device__ __forceinline__ uint32_t sw128(uint32_t off) {
    return off ^ ((off >> 3) & 0x70);
}

// ---------------------------------------------------------------------------
// Problem constants
// ---------------------------------------------------------------------------
#define B_    4
#define T_    32
#define H_    64
#define W_    64
#define COUT_ 64
#define HW_   4096

// K layout: pair p = j = ci*9+kh*3+kw (0..26), halves = kd {t-1, t}.
// Pair 27: A = {1.0, 0}, B = {bias, 0}. MMA covers pairs 0..23 (3 x k16) + 24..27 (k8).
// B row n: tile8=n>>3, jj=n&7 -> cout c=(tile8>>1)*4+(jj>>1), gate=(tile8&1)*2+(jj&1)
// Warp split: mg = wid>>3 (64 px), nq8 = wid&7 (32 n-rows). B frags live in regs.

// SMEM layout (bytes)
#define SM_B_OFF    0                    // B fp16 [256 n][128 B]        = 32768
#define SM_A0_OFF   32768                // A fp16 buffer 0              = 16384
#define SM_A1_OFF   49152                // A fp16 buffer 1              = 16384
#define SM_HALO_OFF 65536                // halo 3 planes x 544 f32      = 6528
#define SM_TOTAL    72064
#define HPLANE      544

#define CT_ 512

__global__ void __launch_bounds__(CT_, 1)
fused_mma_kernel(const float* __restrict__ X,
                 const float* __restrict__ Wc, const float* __restrict__ bconv,
                 const float* __restrict__ Wci, const float* __restrict__ Wcf,
                 const float* __restrict__ Wco, float* __restrict__ out) {
    extern __shared__ __align__(1024) char sm[];
    const uint32_t smb = smem_u32(sm);
    float* hsm = (float*)(sm + SM_HALO_OFF);    // [plane = t mod 3][idx]

    const int tid  = threadIdx.x;
    const int wid  = tid >> 5;
    const int lane = tid & 31;
    const int mg   = wid >> 3;                  // M-half: 64 px
    const int nq8  = wid & 7;                   // N-eighth: 32 gate rows
    const int tile = blockIdx.x;
    const int b    = blockIdx.y;
    const int trow = (tile >> 3) * 16;
    const int tcol = (tile & 7) * 8;

    const float* Xb = X + (size_t)b * 3 * T_ * HW_;

    // ---- prologue: B weights + bias (fp16, SW128), A const cols in BOTH bufs ----
    for (int i = tid; i < 256 * 32; i += CT_) {
        int n = i >> 5;
        int p = i & 31;
        int tile8 = n >> 3;
        int jj    = n & 7;
        int c     = (tile8 >> 1) * 4 + (jj >> 1);
        int gate  = (tile8 & 1) * 2 + (jj & 1);
        int o     = gate * 64 + c;
        float v0 = 0.f, v1 = 0.f;
        if (p < 27) {
            int ci  = p / 9;
            int khw = p - ci * 9;
            v0 = Wc[o * 54 + ci * 18 + khw];
            v1 = Wc[o * 54 + ci * 18 + 9 + khw];
        } else if (p == 27) {
            v0 = bconv[o];
        }
        *(uint32_t*)(sm + SM_B_OFF + sw128((uint32_t)(n * 128 + p * 4))) = f16x2(v1, v0);
    }
    for (int i = tid; i < 128 * 5; i += CT_) {
        int px = i / 5;
        int p  = 27 + (i - px * 5);
        uint32_t v = (p == 27) ? f16x2(0.f, 1.f) : 0u;
        uint32_t arel = sw128((uint32_t)(px * 128 + p * 4));
        *(uint32_t*)(sm + SM_A0_OFF + arel) = v;
        *(uint32_t*)(sm + SM_A1_OFF + arel) = v;
    }

    // ---- halo prefetch descriptors (t-invariant) ----
    int h0idx, h0goff; bool h0ok;
    {
        int i  = tid;                   // 0..511 < 540
        int ci = i / 180;
        int rem = i - ci * 180;
        int rr = rem / 10;
        int cc = rem - rr * 10;
        int hh = trow - 1 + rr;
        int ww = tcol - 1 + cc;
        h0ok   = (hh >= 0 && hh < H_ && ww >= 0 && ww < W_);
        h0idx  = i;
        h0goff = ci * (T_ * HW_) + hh * W_ + ww;
    }
    int h1idx = 0, h1goff = 0; bool h1ok = false;
    if (tid < 28) {
        int i  = tid + 512;
        int ci = i / 180;
        int rem = i - ci * 180;
        int rr = rem / 10;
        int cc = rem - rr * 10;
        int hh = trow - 1 + rr;
        int ww = tcol - 1 + cc;
        h1ok   = (hh >= 0 && hh < H_ && ww >= 0 && ww < W_);
        h1idx  = i;
        h1goff = ci * (T_ * HW_) + hh * W_ + ww;
    }
    // planes: 0 <- x(0), 1 <- x(1), 2 <- 0 (x(-1); (-1) mod 3 == 2)
    hsm[h0idx]              = h0ok ? Xb[h0goff] : 0.f;
    hsm[HPLANE + h0idx]     = h0ok ? Xb[h0goff + HW_] : 0.f;
    hsm[2 * HPLANE + h0idx] = 0.f;
    if (tid < 28) {
        hsm[h1idx]              = h1ok ? Xb[h1goff] : 0.f;
        hsm[HPLANE + h1idx]     = h1ok ? Xb[h1goff + HW_] : 0.f;
        hsm[2 * HPLANE + h1idx] = 0.f;
    }

    // ---- A-build descriptors packed: (swizzled A-rel offset << 10) | halo idx ----
    uint32_t adesc[7];
#pragma unroll
    for (int k = 0; k < 7; k++) {
        int i = tid + k * CT_;
        if (i < 128 * 27) {
            int px = i / 27;
            int p  = i - px * 27;
            int ci  = p / 9;
            int khw = p - ci * 9;
            int kh  = khw / 3;
            int kw  = khw - kh * 3;
            uint32_t asoff = (uint32_t)(ci * 180 + ((px >> 3) + kh) * 10 + ((px & 7) + kw));
            uint32_t arel  = sw128((uint32_t)(px * 128 + p * 4));
            adesc[k] = (arel << 10) | asoff;
        } else {
            adesc[k] = 0xFFFFFFFFu;
        }
    }

    // ---- peephole params -> fp16 registers ----
    // cell m = mt*4 + gg*2 + rs: cout c = (nq8*2+gg)*4 + q,
    //   pixel (h,w) = (trow + mg*8 + mt*2 + rs, tcol + lr)
    const int q  = lane & 3;
    const int lr = lane >> 2;
    const int r8 = lane & 7;
    const int g  = lane >> 3;

    __half2 wifh[16];
    __half2 wcoh[8];
    {
        float wcot[16];
#pragma unroll
        for (int m = 0; m < 16; m++) {
            int mt = m >> 2;
            int gg = (m >> 1) & 1;
            int rs = m & 1;
            int c   = (nq8 * 2 + gg) * 4 + q;
            int hwm = (trow + mg * 8 + mt * 2 + rs) * 64 + tcol + lr;
            wifh[m] = __floats2half2_rn(Wci[c * HW_ + hwm], Wcf[c * HW_ + hwm]);
            wcot[m] = Wco[c * HW_ + hwm];
        }
#pragma unroll
        for (int j = 0; j < 8; j++)
            wcoh[j] = __floats2half2_rn(wcot[2 * j], wcot[2 * j + 1]);
    }
    __syncthreads();    // halo planes + B smem staged

    // ---- preload B fragments to registers (t-invariant!) ----
    const uint32_t cL  = (uint32_t)r8 << 4;
    const uint32_t dkA = (uint32_t)(g >> 1) * 16;
    const uint32_t dkB = (uint32_t)(g & 1) * 16;
    uint32_t Bf[24];    // [gg][kc][4]
    uint32_t Bt[4];     // [gg][2]
#pragma unroll
    for (int gg = 0; gg < 2; gg++) {
        uint32_t bb = smb + SM_B_OFF
                    + (uint32_t)(nq8 * 32 + gg * 16 + r8 + 8 * (g >> 1)) * 128;
#pragma unroll
        for (int kc = 0; kc < 3; kc++)
            ldmatrix_x4(Bf[gg*12+kc*4], Bf[gg*12+kc*4+1],
                        Bf[gg*12+kc*4+2], Bf[gg*12+kc*4+3],
                        bb + ((((uint32_t)kc * 32) + dkB) ^ cL));
        uint32_t bt = smb + SM_B_OFF
                    + (uint32_t)(nq8 * 32 + gg * 16 + (lane & 15)) * 128 + (96u ^ cL);
        ldmatrix_x2(Bt[gg*2], Bt[gg*2+1], bt);
    }

    // ---- prologue A-build(0) into buf 0: v0 = x(-1) (plane 2), v1 = x(0) ----
#pragma unroll
    for (int k = 0; k < 7; k++) {
        uint32_t d = adesc[k];
        if (d != 0xFFFFFFFFu) {
            uint32_t off = d & 1023;
            float v0 = hsm[2 * HPLANE + off];
            float v1 = hsm[off];
            *(uint32_t*)(sm + SM_A0_OFF + (d >> 10)) = f16x2(v1, v0);
        }
    }

    // ---- A ldmatrix lane-constant offsets (buf-relative) ----
    const uint32_t aRow4   = (uint32_t)(mg * 64 + r8 + 8 * (g & 1)) * 128;
    const uint32_t tailRow = (uint32_t)(mg * 64 + (lane & 15)) * 128 + (96u ^ cL);

    // ---- output base ----
    float* outb = out + ((size_t)(b * COUT_ + nq8 * 8 + q)) * (T_ * HW_)
                + (trow + mg * 8) * 64 + tcol + lr;
    const size_t ggstride = (size_t)4 * (T_ * HW_);   // cout += 4 per gg

    float C[16];
#pragma unroll
    for (int m = 0; m < 16; m++) C[m] = 0.f;

    float pf0 = 0.f, pf1 = 0.f;

    for (int t = 0; t < T_; t++) {
        __syncthreads();   // A(t) built; halo plane (t+1)%3 stored; prior reads done

        const int pl0 = t % 3;              // x(t)
        const int pl1 = (t + 1) % 3;        // x(t+1)
        const int pl2 = (t + 2) % 3;        // store target for prefetch

        // ---- prefetch halo plane t+2 (LDG; stored at end of iter) ----
        if (t + 2 < T_) {
            const int toff = (t + 2) * HW_;
            pf0 = h0ok ? Xb[h0goff + toff] : 0.f;
            if (tid < 28) pf1 = h1ok ? Xb[h1goff + toff] : 0.f;
        }

        // ---- A-build(t+1) into buf[(t+1)&1] — overlaps MMA below ----
        if (t + 1 < T_) {
            char* ab = sm + SM_A0_OFF + (size_t)((t + 1) & 1) * 16384;
            const float* hb0 = hsm + pl0 * HPLANE;
            const float* hb1 = hsm + pl1 * HPLANE;
#pragma unroll
            for (int k = 0; k < 7; k++) {
                uint32_t d = adesc[k];
                if (d != 0xFFFFFFFFu) {
                    uint32_t off = d & 1023;
                    float v0 = hb0[off];    // x(t)   (kd=0 for step t+1)
                    float v1 = hb1[off];    // x(t+1) (kd=1)
                    *(uint32_t*)(ab + (d >> 10)) = f16x2(v1, v0);
                }
            }
        }

        // ---- per M16-tile: stream A, MMA vs reg-resident B, recurrence ----
        const uint32_t abuf = smb + (uint32_t)SM_A0_OFF + (uint32_t)(t & 1) * 16384;
        const size_t tof = (size_t)t * HW_;

#pragma unroll
        for (int mt = 0; mt < 4; mt++) {
            float acc[16];
#pragma unroll
            for (int m = 0; m < 16; m++) acc[m] = 0.f;

            const uint32_t aT = abuf + aRow4 + (uint32_t)mt * 2048;
#pragma unroll
            for (int kc = 0; kc < 3; kc++) {
                uint32_t a0, a1, a2, a3;
                ldmatrix_x4(a0, a1, a2, a3, aT + ((((uint32_t)kc * 32) + dkA) ^ cL));
                mma16816(acc,      a0, a1, a2, a3, Bf[kc*4],      Bf[kc*4+1]);
                mma16816(acc + 4,  a0, a1, a2, a3, Bf[kc*4+2],    Bf[kc*4+3]);
                mma16816(acc + 8,  a0, a1, a2, a3, Bf[12+kc*4],   Bf[12+kc*4+1]);
                mma16816(acc + 12, a0, a1, a2, a3, Bf[12+kc*4+2], Bf[12+kc*4+3]);
            }
            {   // k8 tail: pairs 24..27 (incl. bias)
                uint32_t at0, at1;
                ldmatrix_x2(at0, at1, abuf + tailRow + (uint32_t)mt * 2048);
                mma16808(acc,      at0, at1, Bt[0]);
                mma16808(acc + 4,  at0, at1, Bt[1]);
                mma16808(acc + 8,  at0, at1, Bt[2]);
                mma16808(acc + 12, at0, at1, Bt[3]);
            }

            // recurrence: 4 cells = 2 cout-groups x 2 pixel rows
            float* opt = outb + tof + (size_t)(mt * 2) * 64;
#pragma unroll
            for (int gg = 0; gg < 2; gg++) {
                const float* A = acc + gg * 8;   // [i0 f0 i1 f1 | g0 o0 g1 o1]
#pragma unroll
                for (int rs = 0; rs < 2; rs++) {
                    const int m = mt * 4 + gg * 2 + rs;
                    float iv = A[rs * 2];
                    float fv = A[rs * 2 + 1];
                    float gv = A[4 + rs * 2];
                    float ov = A[5 + rs * 2];
                    float2 wif = __half22float2(wifh[m]);
                    float wco  = rs ? __high2float(wcoh[m >> 1])
                                    : __low2float(wcoh[m >> 1]);
                    float Cp = C[m];
                    float ig = sig_fast(iv + wif.x * Cp);
                    float fg = sig_fast(fv + wif.y * Cp);
                    float Cn = fg * Cp + ig * tanh_fast(gv);
                    float og = sig_fast(ov + wco * Cn);
                    opt[gg * ggstride + (size_t)rs * 64] = og * tanh_fast(Cn);
                    C[m] = Cn;
                }
            }
        }

        // ---- store prefetched halo(t+2) into plane pl2 (retired plane) ----
        if (t + 2 < T_) {
            hsm[pl2 * HPLANE + h0idx] = pf0;
            if (tid < 28) hsm[pl2 * HPLANE + h1idx] = pf1;
        }
    }
}

// ---------------------------------------------------------------------------
// kernel_launch
// ---------------------------------------------------------------------------
extern "C" void kernel_launch(void* const* d_in, const int* in_sizes, int n_in,
                              void* d_out, int out_size) {
    const float* X     = (const float*)d_in[0];
    const float* Wc    = (const float*)d_in[1];
    const float* bconv = (const float*)d_in[2];
    const float* Wci   = (const float*)d_in[3];
    const float* Wcf   = (const float*)d_in[4];
    const float* Wco   = (const float*)d_in[5];
    float* out = (float*)d_out;

    cudaFuncSetAttribute(fused_mma_kernel, cudaFuncAttributeMaxDynamicSharedMemorySize,
                         SM_TOTAL);

    dim3 grid(32, B_);   // 32 tiles x 4 batches = 128 CTAs (one wave)
    fused_mma_kernel<<<grid, CT_, SM_TOTAL>>>(X, Wc, bconv, Wci, Wcf, Wco, out);
}